// round 15
// baseline (speedup 1.0000x reference)
#include <cuda_runtime.h>
#include <cuda_bf16.h>
#include <math.h>

// ---------------- static device scratch (no allocations allowed) -------------
__device__ __nv_bfloat16 g_A1b[2048u*2048u];
__device__ float g_A2[1024u*1024u];
__device__ float g_A3[512u*512u];
__device__ float g_h0[4096*64];
__device__ float g_h1[2048*64];
__device__ float g_h2[1024*64];
__device__ float g_ys[4096*64];
__device__ float g_dinv0[4096];
__device__ float g_dinv1[2048];
__device__ float g_dinv2[1024];
__device__ float g_dinv3[512];
__device__ float g_sums2[1024];
__device__ float g_sums3[512];
__device__ int   g_perm0[2048];
__device__ int   g_perm1[1024];
__device__ int   g_perm2[512];
__device__ float g_vals[2048];
__device__ float g_score[4096];
__device__ int   g_cntA[4096];
__device__ int   g_cnt1[2048];
__device__ int   g_idxA[4096u*512u];
__device__ float g_valA[4096u*512u];
__device__ int   g_idx1[2048u*2048u];
__device__ float g_val1[2048u*2048u];
__device__ int   g_sel[4096];

#define ADJ_STRIDE 512
#define A1_STRIDE  2048

// ======= single-pass padded CSR build (adj) + dinv (scalar, ascending) =======
__global__ void k_fillpad(const float* __restrict__ A, int n, int stride,
                          int* __restrict__ idx, float* __restrict__ val,
                          int* __restrict__ cnt, float* __restrict__ dinvOut) {
    int row = blockIdx.x * 8 + (threadIdx.x >> 5);
    int lane = threadIdx.x & 31;
    const float* a = A + (size_t)row * n;
    int* ridx = idx + (size_t)row * stride;
    float* rval = val + (size_t)row * stride;
    int ptr = 0;
    float fsum = 0.f;
    for (int j0 = 0; j0 < n; j0 += 32) {
        float v = a[j0 + lane];
        fsum += v;
        unsigned msk = __ballot_sync(0xffffffffu, v != 0.f);
        if (v != 0.f) {
            int p = ptr + __popc(msk & ((1u << lane) - 1u));
            if (p < stride) { ridx[p] = j0 + lane; rval[p] = v; }
        }
        ptr += __popc(msk);
    }
    for (int o = 16; o; o >>= 1) fsum += __shfl_xor_sync(0xffffffffu, fsum, o);
    if (lane == 0) {
        cnt[row] = (ptr < stride) ? ptr : stride;
        if (dinvOut != 0) dinvOut[row] = 1.0f / sqrtf(fsum + 2.0f);
    }
}

// --------- ys = d .* ((gather(X)) @ W); 32 rows/block, 256 threads -----------
__global__ void __launch_bounds__(256) k_featw(const float* __restrict__ X,
                        const float* __restrict__ W,
                        const float* __restrict__ dinvIn, const float* __restrict__ sums,
                        float* __restrict__ dinvOut,
                        const int* __restrict__ perm, const float* __restrict__ vals,
                        float* __restrict__ ys, int n) {
    __shared__ float Ws[64][64];
    __shared__ float Xs[32][65];
    int tid = threadIdx.x; // 256
    int rowb = blockIdx.x * 32;
    const float4* W4 = (const float4*)W;
    float4* Ws4 = (float4*)&Ws[0][0];
    for (int i = tid; i < 1024; i += 256) Ws4[i] = W4[i];
    for (int i = tid; i < 512; i += 256) {
        int r = i >> 4;
        int c4 = (i & 15) << 2;
        int rs = rowb + r;
        const float* src;
        float scale = 1.f;
        if (perm != 0) { src = X + (size_t)perm[rs] * 64; scale = vals[rs]; }
        else           { src = X + (size_t)rs * 64; }
        float4 v = *(const float4*)(src + c4);
        Xs[r][c4+0] = v.x * scale;
        Xs[r][c4+1] = v.y * scale;
        Xs[r][c4+2] = v.z * scale;
        Xs[r][c4+3] = v.w * scale;
    }
    __syncthreads();
    int tx = tid & 15;
    int ty = tid >> 4;
    float4 acc0 = make_float4(0.f, 0.f, 0.f, 0.f);
    float4 acc1 = make_float4(0.f, 0.f, 0.f, 0.f);
    #pragma unroll 8
    for (int k = 0; k < 64; k++) {
        float4 b = *(float4*)&Ws[k][tx * 4];
        float a0 = Xs[ty*2+0][k];
        float a1 = Xs[ty*2+1][k];
        acc0.x += a0*b.x; acc0.y += a0*b.y; acc0.z += a0*b.z; acc0.w += a0*b.w;
        acc1.x += a1*b.x; acc1.y += a1*b.y; acc1.z += a1*b.z; acc1.w += a1*b.w;
    }
    int r0 = rowb + ty*2;
    float d0, d1;
    if (sums != 0) {
        d0 = 1.0f / sqrtf(sums[r0] + 2.0f);
        d1 = 1.0f / sqrtf(sums[r0 + 1] + 2.0f);
    } else {
        d0 = dinvIn[r0];
        d1 = dinvIn[r0 + 1];
    }
    if (dinvOut != 0 && tx == 0) { dinvOut[r0] = d0; dinvOut[r0 + 1] = d1; }
    float4 o0 = make_float4(acc0.x*d0, acc0.y*d0, acc0.z*d0, acc0.w*d0);
    float4 o1 = make_float4(acc1.x*d1, acc1.y*d1, acc1.z*d1, acc1.w*d1);
    *(float4*)(ys + (size_t)r0 * 64 + tx * 4) = o0;
    *(float4*)(ys + (size_t)(r0 + 1) * 64 + tx * 4) = o1;
}

// ---- padded sparse prop, simple loop (+fused score / +fused final) ----------
__global__ void k_prop_sp(const int* __restrict__ idx, const float* __restrict__ val,
                          const int* __restrict__ cnt, int stride,
                          const float* __restrict__ ys,
                          const float* __restrict__ dinv, const float* __restrict__ bias,
                          float* __restrict__ h, int n, int relu,
                          const int* __restrict__ permOut,
                          const float* __restrict__ pw, float* __restrict__ scoreOut,
                          const float* __restrict__ fcw, const float* __restrict__ fcb,
                          const float* __restrict__ prob, float* __restrict__ finalOut) {
    int row = blockIdx.x * 8 + (threadIdx.x >> 5);
    int lane = threadIdx.x & 31;
    if (row >= n) return;
    const int* ridx = idx + (size_t)row * stride;
    const float* rval = val + (size_t)row * stride;
    int e = cnt[row];
    float a0 = 0.f;
    float a1 = 0.f;
    for (int m = 0; m < e; m++) {
        int j = ridx[m];
        float w = rval[m];
        a0 += w * ys[(size_t)j * 64 + lane];
        a1 += w * ys[(size_t)j * 64 + 32 + lane];
    }
    float d = dinv[row];
    float v0 = d * a0 + 2.f * d * ys[(size_t)row * 64 + lane] + bias[lane];
    float v1 = d * a1 + 2.f * d * ys[(size_t)row * 64 + 32 + lane] + bias[32 + lane];
    if (relu) { v0 = fmaxf(v0, 0.f); v1 = fmaxf(v1, 0.f); }
    if (finalOut != 0) {
        float v = fmaxf(v0, 0.f) * fcw[lane] + fmaxf(v1, 0.f) * fcw[32 + lane];
        for (int o = 16; o; o >>= 1) v += __shfl_xor_sync(0xffffffffu, v, o);
        if (lane == 0) finalOut[row] = v / (1.f - prob[0]) + fcb[0];
        return;
    }
    if (permOut != 0) {
        float* dst = h + (size_t)permOut[row] * 64;
        dst[lane] += v0;
        dst[32 + lane] += v1;
    } else {
        h[(size_t)row * 64 + lane] = v0;
        h[(size_t)row * 64 + 32 + lane] = v1;
    }
    if (scoreOut != 0) {
        float pl = pw[lane];
        float ph = pw[32 + lane];
        float pn = pl*pl + ph*ph;
        float dd = v0 * pl + v1 * ph;
        for (int o = 16; o; o >>= 1) {
            dd += __shfl_xor_sync(0xffffffffu, dd, o);
            pn += __shfl_xor_sync(0xffffffffu, pn, o);
        }
        if (lane == 0) scoreOut[row] = tanhf(dd * (1.0f / sqrtf(pn)));
    }
}

// ------- dense prop: 8 rows/block, ascending-k per output (bit-identical) ----
__global__ void __launch_bounds__(256) k_prop(const float* __restrict__ A,
                       const float* __restrict__ ys,
                       const float* __restrict__ dinv, const float* __restrict__ bias,
                       float* __restrict__ hout, int n, int relu,
                       const int* __restrict__ permOut) {
    __shared__ float sA[8][65];
    __shared__ float sB[64][65];
    int tid = threadIdx.x; // 256
    int tx = tid & 63;
    int ty = tid >> 6;
    int rowb = blockIdx.x * 8;
    float acc0 = 0.f;
    float acc1 = 0.f;
    for (int kb = 0; kb < n; kb += 64) {
        {
            int r = tid >> 5;
            int c2 = (tid & 31) * 2;
            float2 v = *(const float2*)(A + (size_t)(rowb + r) * n + kb + c2);
            sA[r][c2] = v.x;
            sA[r][c2+1] = v.y;
        }
        for (int q = tid; q < 1024; q += 256) {
            int r = q >> 4;
            int c4 = (q & 15) * 4;
            float4 v = *(const float4*)(ys + (size_t)(kb + r) * 64 + c4);
            sB[r][c4] = v.x; sB[r][c4+1] = v.y; sB[r][c4+2] = v.z; sB[r][c4+3] = v.w;
        }
        __syncthreads();
        #pragma unroll 8
        for (int kk = 0; kk < 64; kk++) {
            float b = sB[kk][tx];
            acc0 += sA[ty*2+0][kk] * b;
            acc1 += sA[ty*2+1][kk] * b;
        }
        __syncthreads();
    }
    int r0 = rowb + ty*2;
    int r1 = r0 + 1;
    float d0 = dinv[r0];
    float d1 = dinv[r1];
    float v0 = d0*acc0 + 2.f*d0*ys[(size_t)r0*64 + tx] + bias[tx];
    float v1 = d1*acc1 + 2.f*d1*ys[(size_t)r1*64 + tx] + bias[tx];
    if (relu) { v0 = fmaxf(v0, 0.f); v1 = fmaxf(v1, 0.f); }
    if (permOut != 0) {
        hout[(size_t)permOut[r0]*64 + tx] += v0;
        hout[(size_t)permOut[r1]*64 + tx] += v1;
    } else {
        hout[(size_t)r0*64 + tx] = v0;
        hout[(size_t)r1*64 + tx] = v1;
    }
}

// ---------------- standalone score (level 2 only) ----------------------------
__global__ void k_score(const float* __restrict__ h, const float* __restrict__ p,
                        float* __restrict__ score, int n) {
    int gw = (blockIdx.x * blockDim.x + threadIdx.x) >> 5;
    int lane = threadIdx.x & 31;
    if (gw >= n) return;
    float pl = p[lane];
    float ph = p[32 + lane];
    float pn = pl*pl + ph*ph;
    float d = h[(size_t)gw*64 + lane] * pl + h[(size_t)gw*64 + 32 + lane] * ph;
    for (int o = 16; o; o >>= 1) {
        d  += __shfl_xor_sync(0xffffffffu, d, o);
        pn += __shfl_xor_sync(0xffffffffu, pn, o);
    }
    if (lane == 0) score[gw] = tanhf(d * (1.0f / sqrtf(pn)));
}

// -------- rank-select topk: warp-per-element (8 elems/block) -----------------
__global__ void __launch_bounds__(256) k_rank(const float* __restrict__ score,
                      int n, int k,
                      int* __restrict__ perm, float* __restrict__ vals,
                      int* __restrict__ sel, float* __restrict__ zeroBuf) {
    __shared__ unsigned long long tile[2048];
    int tid = threadIdx.x;  // 256
    int elem = blockIdx.x * 8 + (tid >> 5);
    int part = tid & 31;
    float myscore = score[elem];
    unsigned mb = __float_as_uint(myscore);
    mb = (mb & 0x80000000u) ? (mb ^ 0xFFFFFFFFu) : (mb ^ 0x80000000u);
    unsigned long long my = ((unsigned long long)mb << 32) | (unsigned)(~elem);
    int cnt = 0;
    for (int t0 = 0; t0 < n; t0 += 2048) {
        int tl = n - t0;
        if (tl > 2048) tl = 2048;
        __syncthreads();
        for (int i = tid; i < tl; i += 256) {
            unsigned b = __float_as_uint(score[t0 + i]);
            b = (b & 0x80000000u) ? (b ^ 0xFFFFFFFFu) : (b ^ 0x80000000u);
            tile[i] = ((unsigned long long)b << 32) | (unsigned)(~(t0 + i));
        }
        __syncthreads();
        for (int i = part; i < tl; i += 32) cnt += (tile[i] > my) ? 1 : 0;
    }
    for (int o = 16; o; o >>= 1) cnt += __shfl_xor_sync(0xffffffffu, cnt, o);
    if (part == 0) {
        if (cnt < k) {
            perm[cnt] = elem;
            vals[cnt] = myscore;
            if (sel != 0) sel[elem] = cnt;
            if (zeroBuf != 0) zeroBuf[cnt] = 0.f;
        } else {
            if (sel != 0) sel[elem] = -1;
        }
    }
}

// ------- augment row builder (512 threads): A1 bf16 dense + CSR + dinv1 ------
__global__ void __launch_bounds__(512) k_augrow(const int* __restrict__ idxA,
                         const int* __restrict__ cntA,
                         const int* __restrict__ sel, const int* __restrict__ perm0,
                         __nv_bfloat16* __restrict__ A1b,
                         int* __restrict__ idx1, float* __restrict__ val1,
                         int* __restrict__ cnt1, float* __restrict__ dinv1) {
    __shared__ unsigned counts[2048];
    __shared__ int jlist[528];
    int a = blockIdx.x;
    int pa = perm0[a];
    int tid = threadIdx.x; // 512
    for (int i = tid; i < 2048; i += 512) counts[i] = 0u;
    int na = cntA[pa];
    for (int i = tid; i < na; i += 512) jlist[i] = idxA[(size_t)pa * ADJ_STRIDE + i];
    if (tid == 0) jlist[na] = pa;
    __syncthreads();
    int warp = tid >> 5;
    int lane = tid & 31;
    for (int ji = warp; ji < na + 1; ji += 16) {
        int j = jlist[ji];
        int nj = cntA[j];
        const int* rj = idxA + (size_t)j * ADJ_STRIDE;
        for (int m = lane; m < nj + 1; m += 32) {
            int uu = (m < nj) ? rj[m] : j;
            int s = sel[uu];
            if (s >= 0) atomicAdd(&counts[s], 1u);
        }
    }
    __syncthreads();
    if (tid == 0) counts[a] = 0u; // remove self loop
    __syncthreads();
    unsigned* dst = (unsigned*)(A1b + (size_t)a * 2048);
    for (int i = tid; i < 1024; i += 512) {
        __nv_bfloat162 pr;
        pr.x = __float2bfloat16((float)counts[2*i]);
        pr.y = __float2bfloat16((float)counts[2*i + 1]);
        dst[i] = *(unsigned*)&pr;
    }
    if (warp == 0) {
        int ptr = 0;
        float fsum = 0.f;
        int* ridx = idx1 + (size_t)a * A1_STRIDE;
        float* rval = val1 + (size_t)a * A1_STRIDE;
        for (int j0 = 0; j0 < 2048; j0 += 32) {
            unsigned c = counts[j0 + lane];
            fsum += (float)c;
            unsigned msk = __ballot_sync(0xffffffffu, c != 0u);
            if (c != 0u) {
                int p = ptr + __popc(msk & ((1u << lane) - 1u));
                ridx[p] = j0 + lane;
                rval[p] = (float)c;
            }
            ptr += __popc(msk);
        }
        for (int o = 16; o; o >>= 1) fsum += __shfl_xor_sync(0xffffffffu, fsum, o);
        if (lane == 0) {
            cnt1[a] = ptr;
            dinv1[a] = 1.0f / sqrtf(fsum + 2.0f);
        }
    }
}

// -- bf16 mma ramm, smem-staged tiles (same mma sequence -> bit-identical) ----
__global__ void __launch_bounds__(128) k_ramm_mma_perm(const __nv_bfloat16* __restrict__ Ab,
        const int* __restrict__ perm, float* __restrict__ C, float* __restrict__ sums,
        int k, int m) {
    __shared__ unsigned sTA[64][20];   // 64 rows x 16 uints (32 bf16), stride 20 (cf-free)
    __shared__ unsigned sTB[64][20];
    __shared__ int prA[64];
    __shared__ int prB[64];
    int tid = threadIdx.x; // 128
    int w = tid >> 5;
    int l = tid & 31;
    int lr = l >> 2;
    int lc = l & 3;
    int cb = blockIdx.y * 64;
    if (tid < 64) prA[tid] = perm[blockIdx.x * 64 + tid];
    else          prB[tid - 64] = perm[cb + tid - 64];
    __syncthreads();
    float acc[8][4];
    #pragma unroll
    for (int t = 0; t < 8; t++) {
        #pragma unroll
        for (int j = 0; j < 4; j++) acc[t][j] = 0.f;
    }
    for (int kb = 0; kb < m; kb += 32) {
        for (int q = tid; q < 1024; q += 128) {
            int r = q >> 4;
            int cw = q & 15;
            sTA[r][cw] = ((const unsigned*)(Ab + (size_t)prA[r] * m + kb))[cw];
            sTB[r][cw] = ((const unsigned*)(Ab + (size_t)prB[r] * m + kb))[cw];
        }
        __syncthreads();
        #pragma unroll
        for (int ks = 0; ks < 2; ks++) {
            int off = ks * 8 + lc;
            unsigned a0 = sTA[w*16 + lr][off];
            unsigned a1 = sTA[w*16 + lr + 8][off];
            unsigned a2 = sTA[w*16 + lr][off + 4];
            unsigned a3 = sTA[w*16 + lr + 8][off + 4];
            #pragma unroll
            for (int t = 0; t < 8; t++) {
                unsigned b0 = sTB[t*8 + lr][off];
                unsigned b1 = sTB[t*8 + lr][off + 4];
                asm volatile(
                    "mma.sync.aligned.m16n8k16.row.col.f32.bf16.bf16.f32 "
                    "{%0,%1,%2,%3}, {%4,%5,%6,%7}, {%8,%9}, {%0,%1,%2,%3};"
                    : "+f"(acc[t][0]), "+f"(acc[t][1]), "+f"(acc[t][2]), "+f"(acc[t][3])
                    : "r"(a0), "r"(a1), "r"(a2), "r"(a3), "r"(b0), "r"(b1));
            }
        }
        __syncthreads();
    }
    int row0 = blockIdx.x * 64 + w * 16 + lr;
    int row1 = row0 + 8;
    int ra0 = prA[w*16 + lr];
    int ra1 = prA[w*16 + lr + 8];
    float rs0 = 0.f;
    float rs1 = 0.f;
    #pragma unroll
    for (int t = 0; t < 8; t++) {
        int c0 = cb + t * 8 + lc * 2;
        int c1 = c0 + 1;
        int pc0 = prB[t*8 + lc*2];
        int pc1 = prB[t*8 + lc*2 + 1];
        float v00 = (row0 == c0) ? 0.f : acc[t][0] + 2.f * __bfloat162float(Ab[(size_t)ra0 * m + pc0]);
        float v01 = (row0 == c1) ? 0.f : acc[t][1] + 2.f * __bfloat162float(Ab[(size_t)ra0 * m + pc1]);
        float v10 = (row1 == c0) ? 0.f : acc[t][2] + 2.f * __bfloat162float(Ab[(size_t)ra1 * m + pc0]);
        float v11 = (row1 == c1) ? 0.f : acc[t][3] + 2.f * __bfloat162float(Ab[(size_t)ra1 * m + pc1]);
        *(float2*)&C[(size_t)row0 * k + c0] = make_float2(v00, v01);
        *(float2*)&C[(size_t)row1 * k + c0] = make_float2(v10, v11);
        rs0 += v00 + v01;
        rs1 += v10 + v11;
    }
    if (sums != 0) {
        atomicAdd(&sums[row0], rs0);   // integer-valued: exact, order-free
        atomicAdd(&sums[row1], rs1);
    }
}

// -- fp32 SIMT ramm with perm rows, 32x32 tiles; + atomic row sums ------------
__global__ void __launch_bounds__(256) k_ramm_f32_perm(const float* __restrict__ A,
                                const int* __restrict__ perm,
                                float* __restrict__ C, float* __restrict__ sums,
                                int k, int m) {
    __shared__ float sA[32][33];
    __shared__ float sB[32][33];
    __shared__ int prA[32];
    __shared__ int prB[32];
    int tid = threadIdx.x; // 256
    int tx = tid & 15;
    int ty = tid >> 4;
    int rb = blockIdx.x * 32;
    int cb = blockIdx.y * 32;
    if (tid < 32) prA[tid] = perm[rb + tid];
    else if (tid < 64) prB[tid - 32] = perm[cb + tid - 32];
    __syncthreads();
    float a00 = 0.f, a01 = 0.f, a10 = 0.f, a11 = 0.f;
    for (int kb = 0; kb < m; kb += 32) {
        {
            int r = tid >> 3;
            int c4 = (tid & 7) * 4;
            float4 v = *(const float4*)(A + (size_t)prA[r] * m + kb + c4);
            sA[r][c4] = v.x; sA[r][c4+1] = v.y; sA[r][c4+2] = v.z; sA[r][c4+3] = v.w;
            float4 u = *(const float4*)(A + (size_t)prB[r] * m + kb + c4);
            sB[r][c4] = u.x; sB[r][c4+1] = u.y; sB[r][c4+2] = u.z; sB[r][c4+3] = u.w;
        }
        __syncthreads();
        #pragma unroll
        for (int w = 0; w < 32; w++) {
            float r0 = sA[ty*2+0][w];
            float r1 = sA[ty*2+1][w];
            float c0 = sB[tx*2+0][w];
            float c1 = sB[tx*2+1][w];
            a00 += r0*c0; a01 += r0*c1;
            a10 += r1*c0; a11 += r1*c1;
        }
        __syncthreads();
    }
    int gr0 = rb + ty*2;
    int gr1 = gr0 + 1;
    int gc0 = cb + tx*2;
    int gc1 = gc0 + 1;
    int pr0 = prA[ty*2];
    int pr1 = prA[ty*2+1];
    int pc0 = prB[tx*2];
    int pc1 = prB[tx*2+1];
    float v00 = a00 + 2.f * A[(size_t)pr0 * m + pc0];
    float v01 = a01 + 2.f * A[(size_t)pr0 * m + pc1];
    float v10 = a10 + 2.f * A[(size_t)pr1 * m + pc0];
    float v11 = a11 + 2.f * A[(size_t)pr1 * m + pc1];
    if (gr0 == gc0) v00 = 0.f;
    if (gr0 == gc1) v01 = 0.f;
    if (gr1 == gc0) v10 = 0.f;
    if (gr1 == gc1) v11 = 0.f;
    C[(size_t)gr0 * k + gc0] = v00;
    C[(size_t)gr0 * k + gc1] = v01;
    C[(size_t)gr1 * k + gc0] = v10;
    C[(size_t)gr1 * k + gc1] = v11;
    if (sums != 0) {
        atomicAdd(&sums[gr0], v00 + v01);
        atomicAdd(&sums[gr1], v10 + v11);
    }
}

// =============================================================================
extern "C" void kernel_launch(void* const* d_in, const int* in_sizes, int n_in,
                              void* d_out, int out_size) {
    (void)in_sizes;
    (void)n_in;
    (void)out_size;
    const float* x    = (const float*)d_in[0];
    const float* adj  = (const float*)d_in[1];
    const float* prob = (const float*)d_in[2];
    const float* dW   = (const float*)d_in[3];
    const float* db   = (const float*)d_in[4];
    const float* pw   = (const float*)d_in[5];
    const float* uW   = (const float*)d_in[6];
    const float* ub   = (const float*)d_in[7];
    const float* fcw  = (const float*)d_in[8];
    const float* fcb  = (const float*)d_in[9];
    float* out = (float*)d_out;

    void* pv;
    cudaGetSymbolAddress(&pv, g_A1b);   __nv_bfloat16* A1b = (__nv_bfloat16*)pv;
    cudaGetSymbolAddress(&pv, g_A2);    float* A2 = (float*)pv;
    cudaGetSymbolAddress(&pv, g_A3);    float* A3 = (float*)pv;
    cudaGetSymbolAddress(&pv, g_h0);    float* h0 = (float*)pv;
    cudaGetSymbolAddress(&pv, g_h1);    float* h1 = (float*)pv;
    cudaGetSymbolAddress(&pv, g_h2);    float* h2 = (float*)pv;
    cudaGetSymbolAddress(&pv, g_ys);    float* ys = (float*)pv;
    cudaGetSymbolAddress(&pv, g_dinv0); float* dinv0 = (float*)pv;
    cudaGetSymbolAddress(&pv, g_dinv1); float* dinv1 = (float*)pv;
    cudaGetSymbolAddress(&pv, g_dinv2); float* dinv2 = (float*)pv;
    cudaGetSymbolAddress(&pv, g_dinv3); float* dinv3 = (float*)pv;
    cudaGetSymbolAddress(&pv, g_sums2); float* sums2 = (float*)pv;
    cudaGetSymbolAddress(&pv, g_sums3); float* sums3 = (float*)pv;
    cudaGetSymbolAddress(&pv, g_perm0); int* perm0 = (int*)pv;
    cudaGetSymbolAddress(&pv, g_perm1); int* perm1 = (int*)pv;
    cudaGetSymbolAddress(&pv, g_perm2); int* perm2 = (int*)pv;
    cudaGetSymbolAddress(&pv, g_vals);  float* vals = (float*)pv;
    cudaGetSymbolAddress(&pv, g_score); float* score = (float*)pv;
    cudaGetSymbolAddress(&pv, g_cntA);  int* cntA = (int*)pv;
    cudaGetSymbolAddress(&pv, g_cnt1);  int* cnt1 = (int*)pv;
    cudaGetSymbolAddress(&pv, g_idxA);  int* idxA = (int*)pv;
    cudaGetSymbolAddress(&pv, g_valA);  float* valA = (float*)pv;
    cudaGetSymbolAddress(&pv, g_idx1);  int* idx1 = (int*)pv;
    cudaGetSymbolAddress(&pv, g_val1);  float* val1 = (float*)pv;
    cudaGetSymbolAddress(&pv, g_sel);   int* sel  = (int*)pv;

    const int* np = (const int*)0;
    const float* nv = (const float*)0;
    float* nf = (float*)0;

    // 1. CSR(adj) + dinv0
    k_fillpad<<<512, 256>>>(adj, 4096, ADJ_STRIDE, idxA, valA, cntA, dinv0);
    // 2-3. down L0 + fused score
    k_featw<<<128, 256>>>(x, dW, dinv0, nv, nf, np, nv, ys, 4096);
    k_prop_sp<<<512, 256>>>(idxA, valA, cntA, ADJ_STRIDE, ys, dinv0, db, h0, 4096, 1, np, pw, score, nv, nv, nv, nf);
    // 4. rank-select 4096->2048 (writes sel)
    k_rank<<<512, 256>>>(score, 4096, 2048, perm0, vals, sel, nf);
    // 5. augment: A1 bf16 dense + CSR1 + dinv1
    k_augrow<<<2048, 512>>>(idxA, cntA, sel, perm0, A1b, idx1, val1, cnt1, dinv1);
    // 6-7. down L1 + fused score
    k_featw<<<64, 256>>>(h0, dW + 4096, dinv1, nv, nf, perm0, vals, ys, 2048);
    k_prop_sp<<<256, 256>>>(idx1, val1, cnt1, A1_STRIDE, ys, dinv1, db + 64, h1, 2048, 1, np, pw + 64, score, nv, nv, nv, nf);
    // 8. rank-select 2048->1024 (zeroes sums2)
    k_rank<<<256, 256>>>(score, 2048, 1024, perm1, vals, (int*)0, sums2);
    // 9. A2 = perm-ramm(A1) via mma (smem-staged), + integer-exact rowsums
    k_ramm_mma_perm<<<dim3(16, 16), 128>>>(A1b, perm1, A2, sums2, 1024, 2048);
    // 10-11. down L2 (dinv2 from sums2, written for later reuse)
    k_featw<<<32, 256>>>(h1, dW + 8192, nv, sums2, dinv2, perm1, vals, ys, 1024);
    k_prop<<<128, 256>>>(A2, ys, dinv2, db + 128, h2, 1024, 1, np);
    // 12-13. score + rank-select 1024->512 (zeroes sums3)
    k_score<<<128, 256>>>(h2, pw + 128, score, 1024);
    k_rank<<<128, 256>>>(score, 1024, 512, perm2, vals, (int*)0, sums3);
    // 14. A3 = perm-ramm(A2) fp32 + atomic row sums
    k_ramm_f32_perm<<<dim3(16, 16), 256>>>(A2, perm2, A3, sums3, 512, 1024);
    // 15-16. down L3 (dinv3 from sums3, written out), fused unpool into h2
    k_featw<<<16, 256>>>(h2, dW + 12288, nv, sums3, dinv3, perm2, vals, ys, 512);
    k_prop<<<64, 256>>>(A3, ys, dinv3, db + 192, h2, 512, 1, perm2);
    // 17-18. up0 over A2, fused unpool into h1
    k_featw<<<32, 256>>>(h2, uW, dinv2, nv, nf, np, nv, ys, 1024);
    k_prop<<<128, 256>>>(A2, ys, dinv2, ub, h1, 1024, 1, perm1);
    // 19-20. up1 over A1 (CSR), fused unpool into h0
    k_featw<<<64, 256>>>(h1, uW + 4096, dinv1, nv, nf, np, nv, ys, 2048);
    k_prop_sp<<<256, 256>>>(idx1, val1, cnt1, A1_STRIDE, ys, dinv1, ub + 64, h0, 2048, 1, perm0, nv, nf, nv, nv, nv, nf);
    // 21-22. up2 over adj + fused final (relu, dropout(0), fc)
    k_featw<<<128, 256>>>(h0, uW + 8192, dinv0, nv, nf, np, nv, ys, 4096);
    k_prop_sp<<<512, 256>>>(idxA, valA, cntA, ADJ_STRIDE, ys, dinv0, ub + 128, nf, 4096, 0, np, nv, nf, fcw, fcb, prob, out);
}

// round 16
// speedup vs baseline: 1.3454x; 1.3454x over previous
#include <cuda_runtime.h>
#include <cuda_bf16.h>
#include <math.h>

// ---------------- static device scratch (no allocations allowed) -------------
__device__ __nv_bfloat16 g_A1b[2048u*2048u];
__device__ float g_A2[1024u*1024u];
__device__ float g_A3[512u*512u];
__device__ float g_h0[4096*64];
__device__ float g_h1[2048*64];
__device__ float g_h2[1024*64];
__device__ float g_ys[4096*64];
__device__ float g_dinv0[4096];
__device__ float g_dinv1[2048];
__device__ float g_dinv2[1024];
__device__ float g_dinv3[512];
__device__ float g_sums2[1024];
__device__ float g_sums3[512];
__device__ int   g_perm0[2048];
__device__ int   g_perm1[1024];
__device__ int   g_perm2[512];
__device__ float g_vals[2048];
__device__ float g_score[4096];
__device__ int   g_cntA[4096];
__device__ int   g_cnt1[2048];
__device__ int   g_idxA[4096u*512u];
__device__ float g_valA[4096u*512u];
__device__ int   g_idx1[2048u*2048u];
__device__ float g_val1[2048u*2048u];
__device__ int   g_sel[4096];

#define ADJ_STRIDE 512
#define A1_STRIDE  2048

// ======= single-pass padded CSR build (adj) + dinv (scalar, ascending) =======
__global__ void k_fillpad(const float* __restrict__ A, int n, int stride,
                          int* __restrict__ idx, float* __restrict__ val,
                          int* __restrict__ cnt, float* __restrict__ dinvOut) {
    int row = blockIdx.x * 8 + (threadIdx.x >> 5);
    int lane = threadIdx.x & 31;
    const float* a = A + (size_t)row * n;
    int* ridx = idx + (size_t)row * stride;
    float* rval = val + (size_t)row * stride;
    int ptr = 0;
    float fsum = 0.f;
    for (int j0 = 0; j0 < n; j0 += 32) {
        float v = a[j0 + lane];
        fsum += v;
        unsigned msk = __ballot_sync(0xffffffffu, v != 0.f);
        if (v != 0.f) {
            int p = ptr + __popc(msk & ((1u << lane) - 1u));
            if (p < stride) { ridx[p] = j0 + lane; rval[p] = v; }
        }
        ptr += __popc(msk);
    }
    for (int o = 16; o; o >>= 1) fsum += __shfl_xor_sync(0xffffffffu, fsum, o);
    if (lane == 0) {
        cnt[row] = (ptr < stride) ? ptr : stride;
        if (dinvOut != 0) dinvOut[row] = 1.0f / sqrtf(fsum + 2.0f);
    }
}

// --------- ys = d .* ((gather(X)) @ W); 32 rows/block, 256 threads -----------
__global__ void __launch_bounds__(256) k_featw(const float* __restrict__ X,
                        const float* __restrict__ W,
                        const float* __restrict__ dinvIn, const float* __restrict__ sums,
                        float* __restrict__ dinvOut,
                        const int* __restrict__ perm, const float* __restrict__ vals,
                        float* __restrict__ ys, int n) {
    __shared__ float Ws[64][64];
    __shared__ float Xs[32][65];
    int tid = threadIdx.x; // 256
    int rowb = blockIdx.x * 32;
    const float4* W4 = (const float4*)W;
    float4* Ws4 = (float4*)&Ws[0][0];
    for (int i = tid; i < 1024; i += 256) Ws4[i] = W4[i];
    for (int i = tid; i < 512; i += 256) {
        int r = i >> 4;
        int c4 = (i & 15) << 2;
        int rs = rowb + r;
        const float* src;
        float scale = 1.f;
        if (perm != 0) { src = X + (size_t)perm[rs] * 64; scale = vals[rs]; }
        else           { src = X + (size_t)rs * 64; }
        float4 v = *(const float4*)(src + c4);
        Xs[r][c4+0] = v.x * scale;
        Xs[r][c4+1] = v.y * scale;
        Xs[r][c4+2] = v.z * scale;
        Xs[r][c4+3] = v.w * scale;
    }
    __syncthreads();
    int tx = tid & 15;
    int ty = tid >> 4;
    float4 acc0 = make_float4(0.f, 0.f, 0.f, 0.f);
    float4 acc1 = make_float4(0.f, 0.f, 0.f, 0.f);
    #pragma unroll 8
    for (int k = 0; k < 64; k++) {
        float4 b = *(float4*)&Ws[k][tx * 4];
        float a0 = Xs[ty*2+0][k];
        float a1 = Xs[ty*2+1][k];
        acc0.x += a0*b.x; acc0.y += a0*b.y; acc0.z += a0*b.z; acc0.w += a0*b.w;
        acc1.x += a1*b.x; acc1.y += a1*b.y; acc1.z += a1*b.z; acc1.w += a1*b.w;
    }
    int r0 = rowb + ty*2;
    float d0, d1;
    if (sums != 0) {
        d0 = 1.0f / sqrtf(sums[r0] + 2.0f);
        d1 = 1.0f / sqrtf(sums[r0 + 1] + 2.0f);
    } else {
        d0 = dinvIn[r0];
        d1 = dinvIn[r0 + 1];
    }
    if (dinvOut != 0 && tx == 0) { dinvOut[r0] = d0; dinvOut[r0 + 1] = d1; }
    float4 o0 = make_float4(acc0.x*d0, acc0.y*d0, acc0.z*d0, acc0.w*d0);
    float4 o1 = make_float4(acc1.x*d1, acc1.y*d1, acc1.z*d1, acc1.w*d1);
    *(float4*)(ys + (size_t)r0 * 64 + tx * 4) = o0;
    *(float4*)(ys + (size_t)(r0 + 1) * 64 + tx * 4) = o1;
}

// ---- padded sparse prop, simple loop (+fused score / +fused final) ----------
__global__ void k_prop_sp(const int* __restrict__ idx, const float* __restrict__ val,
                          const int* __restrict__ cnt, int stride,
                          const float* __restrict__ ys,
                          const float* __restrict__ dinv, const float* __restrict__ bias,
                          float* __restrict__ h, int n, int relu,
                          const int* __restrict__ permOut,
                          const float* __restrict__ pw, float* __restrict__ scoreOut,
                          const float* __restrict__ fcw, const float* __restrict__ fcb,
                          const float* __restrict__ prob, float* __restrict__ finalOut) {
    int row = blockIdx.x * 8 + (threadIdx.x >> 5);
    int lane = threadIdx.x & 31;
    if (row >= n) return;
    const int* ridx = idx + (size_t)row * stride;
    const float* rval = val + (size_t)row * stride;
    int e = cnt[row];
    float a0 = 0.f;
    float a1 = 0.f;
    for (int m = 0; m < e; m++) {
        int j = ridx[m];
        float w = rval[m];
        a0 += w * ys[(size_t)j * 64 + lane];
        a1 += w * ys[(size_t)j * 64 + 32 + lane];
    }
    float d = dinv[row];
    float v0 = d * a0 + 2.f * d * ys[(size_t)row * 64 + lane] + bias[lane];
    float v1 = d * a1 + 2.f * d * ys[(size_t)row * 64 + 32 + lane] + bias[32 + lane];
    if (relu) { v0 = fmaxf(v0, 0.f); v1 = fmaxf(v1, 0.f); }
    if (finalOut != 0) {
        float v = fmaxf(v0, 0.f) * fcw[lane] + fmaxf(v1, 0.f) * fcw[32 + lane];
        for (int o = 16; o; o >>= 1) v += __shfl_xor_sync(0xffffffffu, v, o);
        if (lane == 0) finalOut[row] = v / (1.f - prob[0]) + fcb[0];
        return;
    }
    if (permOut != 0) {
        float* dst = h + (size_t)permOut[row] * 64;
        dst[lane] += v0;
        dst[32 + lane] += v1;
    } else {
        h[(size_t)row * 64 + lane] = v0;
        h[(size_t)row * 64 + 32 + lane] = v1;
    }
    if (scoreOut != 0) {
        float pl = pw[lane];
        float ph = pw[32 + lane];
        float pn = pl*pl + ph*ph;
        float dd = v0 * pl + v1 * ph;
        for (int o = 16; o; o >>= 1) {
            dd += __shfl_xor_sync(0xffffffffu, dd, o);
            pn += __shfl_xor_sync(0xffffffffu, pn, o);
        }
        if (lane == 0) scoreOut[row] = tanhf(dd * (1.0f / sqrtf(pn)));
    }
}

// ------- dense prop: 8 rows/block, ascending-k per output (bit-identical) ----
__global__ void __launch_bounds__(256) k_prop(const float* __restrict__ A,
                       const float* __restrict__ ys,
                       const float* __restrict__ dinv, const float* __restrict__ bias,
                       float* __restrict__ hout, int n, int relu,
                       const int* __restrict__ permOut) {
    __shared__ float sA[8][65];
    __shared__ float sB[64][65];
    int tid = threadIdx.x; // 256
    int tx = tid & 63;
    int ty = tid >> 6;
    int rowb = blockIdx.x * 8;
    float acc0 = 0.f;
    float acc1 = 0.f;
    for (int kb = 0; kb < n; kb += 64) {
        {
            int r = tid >> 5;
            int c2 = (tid & 31) * 2;
            float2 v = *(const float2*)(A + (size_t)(rowb + r) * n + kb + c2);
            sA[r][c2] = v.x;
            sA[r][c2+1] = v.y;
        }
        for (int q = tid; q < 1024; q += 256) {
            int r = q >> 4;
            int c4 = (q & 15) * 4;
            float4 v = *(const float4*)(ys + (size_t)(kb + r) * 64 + c4);
            sB[r][c4] = v.x; sB[r][c4+1] = v.y; sB[r][c4+2] = v.z; sB[r][c4+3] = v.w;
        }
        __syncthreads();
        #pragma unroll 8
        for (int kk = 0; kk < 64; kk++) {
            float b = sB[kk][tx];
            acc0 += sA[ty*2+0][kk] * b;
            acc1 += sA[ty*2+1][kk] * b;
        }
        __syncthreads();
    }
    int r0 = rowb + ty*2;
    int r1 = r0 + 1;
    float d0 = dinv[r0];
    float d1 = dinv[r1];
    float v0 = d0*acc0 + 2.f*d0*ys[(size_t)r0*64 + tx] + bias[tx];
    float v1 = d1*acc1 + 2.f*d1*ys[(size_t)r1*64 + tx] + bias[tx];
    if (relu) { v0 = fmaxf(v0, 0.f); v1 = fmaxf(v1, 0.f); }
    if (permOut != 0) {
        hout[(size_t)permOut[r0]*64 + tx] += v0;
        hout[(size_t)permOut[r1]*64 + tx] += v1;
    } else {
        hout[(size_t)r0*64 + tx] = v0;
        hout[(size_t)r1*64 + tx] = v1;
    }
}

// ---------------- standalone score (level 2 only) ----------------------------
__global__ void k_score(const float* __restrict__ h, const float* __restrict__ p,
                        float* __restrict__ score, int n) {
    int gw = (blockIdx.x * blockDim.x + threadIdx.x) >> 5;
    int lane = threadIdx.x & 31;
    if (gw >= n) return;
    float pl = p[lane];
    float ph = p[32 + lane];
    float pn = pl*pl + ph*ph;
    float d = h[(size_t)gw*64 + lane] * pl + h[(size_t)gw*64 + 32 + lane] * ph;
    for (int o = 16; o; o >>= 1) {
        d  += __shfl_xor_sync(0xffffffffu, d, o);
        pn += __shfl_xor_sync(0xffffffffu, pn, o);
    }
    if (lane == 0) score[gw] = tanhf(d * (1.0f / sqrtf(pn)));
}

// -------- rank-select topk: warp-per-element (8 elems/block) -----------------
__global__ void __launch_bounds__(256) k_rank(const float* __restrict__ score,
                      int n, int k,
                      int* __restrict__ perm, float* __restrict__ vals,
                      int* __restrict__ sel, float* __restrict__ zeroBuf) {
    __shared__ unsigned long long tile[2048];
    int tid = threadIdx.x;  // 256
    int elem = blockIdx.x * 8 + (tid >> 5);
    int part = tid & 31;
    float myscore = score[elem];
    unsigned mb = __float_as_uint(myscore);
    mb = (mb & 0x80000000u) ? (mb ^ 0xFFFFFFFFu) : (mb ^ 0x80000000u);
    unsigned long long my = ((unsigned long long)mb << 32) | (unsigned)(~elem);
    int cnt = 0;
    for (int t0 = 0; t0 < n; t0 += 2048) {
        int tl = n - t0;
        if (tl > 2048) tl = 2048;
        __syncthreads();
        for (int i = tid; i < tl; i += 256) {
            unsigned b = __float_as_uint(score[t0 + i]);
            b = (b & 0x80000000u) ? (b ^ 0xFFFFFFFFu) : (b ^ 0x80000000u);
            tile[i] = ((unsigned long long)b << 32) | (unsigned)(~(t0 + i));
        }
        __syncthreads();
        for (int i = part; i < tl; i += 32) cnt += (tile[i] > my) ? 1 : 0;
    }
    for (int o = 16; o; o >>= 1) cnt += __shfl_xor_sync(0xffffffffu, cnt, o);
    if (part == 0) {
        if (cnt < k) {
            perm[cnt] = elem;
            vals[cnt] = myscore;
            if (sel != 0) sel[elem] = cnt;
            if (zeroBuf != 0) zeroBuf[cnt] = 0.f;
        } else {
            if (sel != 0) sel[elem] = -1;
        }
    }
}

// ------- augment row builder: A1 bf16 dense row + CSR row + dinv1 ------------
__global__ void k_augrow(const int* __restrict__ idxA, const int* __restrict__ cntA,
                         const int* __restrict__ sel, const int* __restrict__ perm0,
                         __nv_bfloat16* __restrict__ A1b,
                         int* __restrict__ idx1, float* __restrict__ val1,
                         int* __restrict__ cnt1, float* __restrict__ dinv1) {
    __shared__ unsigned counts[2048];
    __shared__ int jlist[528];
    int a = blockIdx.x;
    int pa = perm0[a];
    int tid = threadIdx.x; // 256
    for (int i = tid; i < 2048; i += 256) counts[i] = 0u;
    int na = cntA[pa];
    for (int i = tid; i < na; i += 256) jlist[i] = idxA[(size_t)pa * ADJ_STRIDE + i];
    if (tid == 0) jlist[na] = pa;
    __syncthreads();
    int warp = tid >> 5;
    int lane = tid & 31;
    for (int ji = warp; ji < na + 1; ji += 8) {
        int j = jlist[ji];
        int nj = cntA[j];
        const int* rj = idxA + (size_t)j * ADJ_STRIDE;
        for (int m = lane; m < nj + 1; m += 32) {
            int uu = (m < nj) ? rj[m] : j;
            int s = sel[uu];
            if (s >= 0) atomicAdd(&counts[s], 1u);
        }
    }
    __syncthreads();
    if (tid == 0) counts[a] = 0u; // remove self loop
    __syncthreads();
    unsigned* dst = (unsigned*)(A1b + (size_t)a * 2048);
    for (int i = tid; i < 1024; i += 256) {
        __nv_bfloat162 pr;
        pr.x = __float2bfloat16((float)counts[2*i]);
        pr.y = __float2bfloat16((float)counts[2*i + 1]);
        dst[i] = *(unsigned*)&pr;
    }
    if (warp == 0) {
        int ptr = 0;
        float fsum = 0.f;
        int* ridx = idx1 + (size_t)a * A1_STRIDE;
        float* rval = val1 + (size_t)a * A1_STRIDE;
        for (int j0 = 0; j0 < 2048; j0 += 32) {
            unsigned c = counts[j0 + lane];
            fsum += (float)c;
            unsigned msk = __ballot_sync(0xffffffffu, c != 0u);
            if (c != 0u) {
                int p = ptr + __popc(msk & ((1u << lane) - 1u));
                ridx[p] = j0 + lane;
                rval[p] = (float)c;
            }
            ptr += __popc(msk);
        }
        for (int o = 16; o; o >>= 1) fsum += __shfl_xor_sync(0xffffffffu, fsum, o);
        if (lane == 0) {
            cnt1[a] = ptr;
            dinv1[a] = 1.0f / sqrtf(fsum + 2.0f);
        }
    }
}

// -- bf16 mma ramm with perm rows: C = dot(A[pa],A[pb]) + 2A[pa][pb]; +rowsums
__global__ void __launch_bounds__(128) k_ramm_mma_perm(const __nv_bfloat16* __restrict__ Ab,
        const int* __restrict__ perm, float* __restrict__ C, float* __restrict__ sums,
        int k, int m) {
    int w = threadIdx.x >> 5;
    int l = threadIdx.x & 31;
    int rb = blockIdx.x * 64 + w * 16;
    int cb = blockIdx.y * 64;
    int lr = l >> 2;
    int lc = l & 3;
    int ra0 = perm[rb + lr];
    int ra1 = perm[rb + lr + 8];
    int rbv[8];
    #pragma unroll
    for (int t = 0; t < 8; t++) rbv[t] = perm[cb + t*8 + lr];
    float acc[8][4];
    #pragma unroll
    for (int t = 0; t < 8; t++) {
        #pragma unroll
        for (int j = 0; j < 4; j++) acc[t][j] = 0.f;
    }
    const unsigned* A0 = (const unsigned*)(Ab + (size_t)ra0 * m) + lc;
    const unsigned* A1r = (const unsigned*)(Ab + (size_t)ra1 * m) + lc;
    for (int kb = 0; kb < m; kb += 16) {
        int kw = kb >> 1;
        unsigned a0 = A0[kw];
        unsigned a1 = A1r[kw];
        unsigned a2 = A0[kw + 4];
        unsigned a3 = A1r[kw + 4];
        #pragma unroll
        for (int t = 0; t < 8; t++) {
            const unsigned* Bp = (const unsigned*)(Ab + (size_t)rbv[t] * m) + lc;
            unsigned b0 = Bp[kw];
            unsigned b1 = Bp[kw + 4];
            asm volatile(
                "mma.sync.aligned.m16n8k16.row.col.f32.bf16.bf16.f32 "
                "{%0,%1,%2,%3}, {%4,%5,%6,%7}, {%8,%9}, {%0,%1,%2,%3};"
                : "+f"(acc[t][0]), "+f"(acc[t][1]), "+f"(acc[t][2]), "+f"(acc[t][3])
                : "r"(a0), "r"(a1), "r"(a2), "r"(a3), "r"(b0), "r"(b1));
        }
    }
    int row0 = rb + lr;
    int row1 = rb + lr + 8;
    float rs0 = 0.f;
    float rs1 = 0.f;
    #pragma unroll
    for (int t = 0; t < 8; t++) {
        int c0 = cb + t * 8 + lc * 2;
        int c1 = c0 + 1;
        int pc0 = perm[c0];
        int pc1 = perm[c1];
        float v00 = (row0 == c0) ? 0.f : acc[t][0] + 2.f * __bfloat162float(Ab[(size_t)ra0 * m + pc0]);
        float v01 = (row0 == c1) ? 0.f : acc[t][1] + 2.f * __bfloat162float(Ab[(size_t)ra0 * m + pc1]);
        float v10 = (row1 == c0) ? 0.f : acc[t][2] + 2.f * __bfloat162float(Ab[(size_t)ra1 * m + pc0]);
        float v11 = (row1 == c1) ? 0.f : acc[t][3] + 2.f * __bfloat162float(Ab[(size_t)ra1 * m + pc1]);
        *(float2*)&C[(size_t)row0 * k + c0] = make_float2(v00, v01);
        *(float2*)&C[(size_t)row1 * k + c0] = make_float2(v10, v11);
        rs0 += v00 + v01;
        rs1 += v10 + v11;
    }
    if (sums != 0) {
        atomicAdd(&sums[row0], rs0);
        atomicAdd(&sums[row1], rs1);
    }
}

// -- fp32 SIMT ramm with perm rows, 32x32 tiles; + atomic row sums ------------
__global__ void __launch_bounds__(256) k_ramm_f32_perm(const float* __restrict__ A,
                                const int* __restrict__ perm,
                                float* __restrict__ C, float* __restrict__ sums,
                                int k, int m) {
    __shared__ float sA[32][33];
    __shared__ float sB[32][33];
    __shared__ int prA[32];
    __shared__ int prB[32];
    int tid = threadIdx.x; // 256
    int tx = tid & 15;
    int ty = tid >> 4;
    int rb = blockIdx.x * 32;
    int cb = blockIdx.y * 32;
    if (tid < 32) prA[tid] = perm[rb + tid];
    else if (tid < 64) prB[tid - 32] = perm[cb + tid - 32];
    __syncthreads();
    float a00 = 0.f, a01 = 0.f, a10 = 0.f, a11 = 0.f;
    for (int kb = 0; kb < m; kb += 32) {
        {
            int r = tid >> 3;
            int c4 = (tid & 7) * 4;
            float4 v = *(const float4*)(A + (size_t)prA[r] * m + kb + c4);
            sA[r][c4] = v.x; sA[r][c4+1] = v.y; sA[r][c4+2] = v.z; sA[r][c4+3] = v.w;
            float4 u = *(const float4*)(A + (size_t)prB[r] * m + kb + c4);
            sB[r][c4] = u.x; sB[r][c4+1] = u.y; sB[r][c4+2] = u.z; sB[r][c4+3] = u.w;
        }
        __syncthreads();
        #pragma unroll
        for (int w = 0; w < 32; w++) {
            float r0 = sA[ty*2+0][w];
            float r1 = sA[ty*2+1][w];
            float c0 = sB[tx*2+0][w];
            float c1 = sB[tx*2+1][w];
            a00 += r0*c0; a01 += r0*c1;
            a10 += r1*c0; a11 += r1*c1;
        }
        __syncthreads();
    }
    int gr0 = rb + ty*2;
    int gr1 = gr0 + 1;
    int gc0 = cb + tx*2;
    int gc1 = gc0 + 1;
    int pr0 = prA[ty*2];
    int pr1 = prA[ty*2+1];
    int pc0 = prB[tx*2];
    int pc1 = prB[tx*2+1];
    float v00 = a00 + 2.f * A[(size_t)pr0 * m + pc0];
    float v01 = a01 + 2.f * A[(size_t)pr0 * m + pc1];
    float v10 = a10 + 2.f * A[(size_t)pr1 * m + pc0];
    float v11 = a11 + 2.f * A[(size_t)pr1 * m + pc1];
    if (gr0 == gc0) v00 = 0.f;
    if (gr0 == gc1) v01 = 0.f;
    if (gr1 == gc0) v10 = 0.f;
    if (gr1 == gc1) v11 = 0.f;
    C[(size_t)gr0 * k + gc0] = v00;
    C[(size_t)gr0 * k + gc1] = v01;
    C[(size_t)gr1 * k + gc0] = v10;
    C[(size_t)gr1 * k + gc1] = v11;
    if (sums != 0) {
        atomicAdd(&sums[gr0], v00 + v01);
        atomicAdd(&sums[gr1], v10 + v11);
    }
}

// =============================================================================
extern "C" void kernel_launch(void* const* d_in, const int* in_sizes, int n_in,
                              void* d_out, int out_size) {
    (void)in_sizes;
    (void)n_in;
    (void)out_size;
    const float* x    = (const float*)d_in[0];
    const float* adj  = (const float*)d_in[1];
    const float* prob = (const float*)d_in[2];
    const float* dW   = (const float*)d_in[3];
    const float* db   = (const float*)d_in[4];
    const float* pw   = (const float*)d_in[5];
    const float* uW   = (const float*)d_in[6];
    const float* ub   = (const float*)d_in[7];
    const float* fcw  = (const float*)d_in[8];
    const float* fcb  = (const float*)d_in[9];
    float* out = (float*)d_out;

    void* pv;
    cudaGetSymbolAddress(&pv, g_A1b);   __nv_bfloat16* A1b = (__nv_bfloat16*)pv;
    cudaGetSymbolAddress(&pv, g_A2);    float* A2 = (float*)pv;
    cudaGetSymbolAddress(&pv, g_A3);    float* A3 = (float*)pv;
    cudaGetSymbolAddress(&pv, g_h0);    float* h0 = (float*)pv;
    cudaGetSymbolAddress(&pv, g_h1);    float* h1 = (float*)pv;
    cudaGetSymbolAddress(&pv, g_h2);    float* h2 = (float*)pv;
    cudaGetSymbolAddress(&pv, g_ys);    float* ys = (float*)pv;
    cudaGetSymbolAddress(&pv, g_dinv0); float* dinv0 = (float*)pv;
    cudaGetSymbolAddress(&pv, g_dinv1); float* dinv1 = (float*)pv;
    cudaGetSymbolAddress(&pv, g_dinv2); float* dinv2 = (float*)pv;
    cudaGetSymbolAddress(&pv, g_dinv3); float* dinv3 = (float*)pv;
    cudaGetSymbolAddress(&pv, g_sums2); float* sums2 = (float*)pv;
    cudaGetSymbolAddress(&pv, g_sums3); float* sums3 = (float*)pv;
    cudaGetSymbolAddress(&pv, g_perm0); int* perm0 = (int*)pv;
    cudaGetSymbolAddress(&pv, g_perm1); int* perm1 = (int*)pv;
    cudaGetSymbolAddress(&pv, g_perm2); int* perm2 = (int*)pv;
    cudaGetSymbolAddress(&pv, g_vals);  float* vals = (float*)pv;
    cudaGetSymbolAddress(&pv, g_score); float* score = (float*)pv;
    cudaGetSymbolAddress(&pv, g_cntA);  int* cntA = (int*)pv;
    cudaGetSymbolAddress(&pv, g_cnt1);  int* cnt1 = (int*)pv;
    cudaGetSymbolAddress(&pv, g_idxA);  int* idxA = (int*)pv;
    cudaGetSymbolAddress(&pv, g_valA);  float* valA = (float*)pv;
    cudaGetSymbolAddress(&pv, g_idx1);  int* idx1 = (int*)pv;
    cudaGetSymbolAddress(&pv, g_val1);  float* val1 = (float*)pv;
    cudaGetSymbolAddress(&pv, g_sel);   int* sel  = (int*)pv;

    const int* np = (const int*)0;
    const float* nv = (const float*)0;
    float* nf = (float*)0;

    // 1. CSR(adj) + dinv0
    k_fillpad<<<512, 256>>>(adj, 4096, ADJ_STRIDE, idxA, valA, cntA, dinv0);
    // 2-3. down L0 + fused score
    k_featw<<<128, 256>>>(x, dW, dinv0, nv, nf, np, nv, ys, 4096);
    k_prop_sp<<<512, 256>>>(idxA, valA, cntA, ADJ_STRIDE, ys, dinv0, db, h0, 4096, 1, np, pw, score, nv, nv, nv, nf);
    // 4. rank-select 4096->2048 (writes sel)
    k_rank<<<512, 256>>>(score, 4096, 2048, perm0, vals, sel, nf);
    // 5. augment: A1 bf16 dense + CSR1 + dinv1
    k_augrow<<<2048, 256>>>(idxA, cntA, sel, perm0, A1b, idx1, val1, cnt1, dinv1);
    // 6-7. down L1 + fused score
    k_featw<<<64, 256>>>(h0, dW + 4096, dinv1, nv, nf, perm0, vals, ys, 2048);
    k_prop_sp<<<256, 256>>>(idx1, val1, cnt1, A1_STRIDE, ys, dinv1, db + 64, h1, 2048, 1, np, pw + 64, score, nv, nv, nv, nf);
    // 8. rank-select 2048->1024 (zeroes sums2)
    k_rank<<<256, 256>>>(score, 2048, 1024, perm1, vals, (int*)0, sums2);
    // 9. A2 = perm-ramm(A1) via mma, + integer-exact rowsums
    k_ramm_mma_perm<<<dim3(16, 16), 128>>>(A1b, perm1, A2, sums2, 1024, 2048);
    // 10-11. down L2 (dinv2 from sums2, written for later reuse)
    k_featw<<<32, 256>>>(h1, dW + 8192, nv, sums2, dinv2, perm1, vals, ys, 1024);
    k_prop<<<128, 256>>>(A2, ys, dinv2, db + 128, h2, 1024, 1, np);
    // 12-13. score + rank-select 1024->512 (zeroes sums3)
    k_score<<<128, 256>>>(h2, pw + 128, score, 1024);
    k_rank<<<128, 256>>>(score, 1024, 512, perm2, vals, (int*)0, sums3);
    // 14. A3 = perm-ramm(A2) fp32 + atomic row sums
    k_ramm_f32_perm<<<dim3(16, 16), 256>>>(A2, perm2, A3, sums3, 512, 1024);
    // 15-16. down L3 (dinv3 from sums3, written out), fused unpool into h2
    k_featw<<<16, 256>>>(h2, dW + 12288, nv, sums3, dinv3, perm2, vals, ys, 512);
    k_prop<<<64, 256>>>(A3, ys, dinv3, db + 192, h2, 512, 1, perm2);
    // 17-18. up0 over A2, fused unpool into h1
    k_featw<<<32, 256>>>(h2, uW, dinv2, nv, nf, np, nv, ys, 1024);
    k_prop<<<128, 256>>>(A2, ys, dinv2, ub, h1, 1024, 1, perm1);
    // 19-20. up1 over A1 (CSR), fused unpool into h0
    k_featw<<<64, 256>>>(h1, uW + 4096, dinv1, nv, nf, np, nv, ys, 2048);
    k_prop_sp<<<256, 256>>>(idx1, val1, cnt1, A1_STRIDE, ys, dinv1, ub + 64, h0, 2048, 1, perm0, nv, nf, nv, nv, nv, nf);
    // 21-22. up2 over adj + fused final (relu, dropout(0), fc)
    k_featw<<<128, 256>>>(h0, uW + 8192, dinv0, nv, nf, np, nv, ys, 4096);
    k_prop_sp<<<512, 256>>>(idxA, valA, cntA, ADJ_STRIDE, ys, dinv0, ub + 128, nf, 4096, 0, np, nv, nf, fcw, fcb, prob, out);
}